// round 8
// baseline (speedup 1.0000x reference)
#include <cuda_runtime.h>
#include <cstdint>

// DeformConv2d (KS=3, PAD=1, STRIDE=1, RATIO=1) on x:(4,32,256,256) f32.
// Integer positions => exact gather from reflection-padded input:
//   out[b,c, 3i+kx, 3j+ky] = mx*my * xp[b,c, i+kx, j+ky]
//   mx,my = 2 iff padded index == 257 (upper clamp aliasing), else 1.
//   xp[0]=x[1], xp[257]=x[254], xp[p]=x[p-1] (reflect, edge excluded).
//
// Block = 8 input rows of one (b,c): build 10 resolved padded rows in smem
// ONCE (column reflect + column x2 folded; row x2 applied only in the single
// affected warp-uniform branch), then 24 output rows of pure shuffle-stores:
// per output float4: 2x LDS.128 + 6 SEL + 1 coalesced STG.128.

#define H 256
#define W 256
#define OH 768
#define OW 768
#define R 8            // input rows per block
#define PR (R + 2)     // padded rows resident
#define RPS 264        // smem row stride (floats)
#define NT 384         // threads per block

__global__ __launch_bounds__(NT, 4)
void deform_sample_kernel(const float* __restrict__ x, float* __restrict__ out) {
    __shared__ float rp[PR][RPS];

    const int ib = blockIdx.x * R;          // first input row: 0,8,...,248
    const int bc = blockIdx.y;              // 0..127
    const int t  = threadIdx.x;             // 0..383

    const float* xb = x + (size_t)bc * H * W;

    // ---- Fill: 10 resolved padded rows (column-resolved; row mult deferred) ----
    // Bulk: p in [1,256] -> x[sx][p-1], coalesced scalar.
    for (int idx = t; idx < PR * W; idx += NT) {
        const int prow = idx >> 8;                  // /256
        const int c    = idx & 255;                 // p-1
        const int px   = ib + prow;                 // 0..257
        const int sx   = (px == 0) ? 1 : (px == H + 1) ? (H - 2) : (px - 1);
        rp[prow][c + 1] = xb[sx * W + c];
    }
    // Edges: p=0 -> x[sx][1];  p=257 -> 2*x[sx][254]  (column x2 folded here)
    if (t < 2 * PR) {
        const int prow = t >> 1;
        const int px   = ib + prow;
        const int sx   = (px == 0) ? 1 : (px == H + 1) ? (H - 2) : (px - 1);
        if ((t & 1) == 0) rp[prow][0]     = xb[sx * W + 1];
        else              rp[prow][W + 1] = 2.0f * xb[sx * W + (W - 2)];
    }
    __syncthreads();

    // ---- Store: 24 output rows x 192 float4 ----
    // Thread: q = t % 192 fixed; half = t / 192 covers rows half*12 .. half*12+11.
    const int q    = (t >= 192) ? t - 192 : t;
    const int half = (t >= 192) ? 1 : 0;
    const int m = q / 3;
    const int r = q - 3 * m;

    // padded-row index for output-row offset ro: prow = ro/3 + ro%3
    // row x2 only when px == 257 <=> ib == 248 && prow == 9 (rows ro = 23 only)
    const bool lastblk = (ib == H - R);

    float* ob = out + ((size_t)bc * OH + (size_t)ib * 3 + half * 12) * OW + 4 * q;

#pragma unroll
    for (int s = 0; s < 12; s++) {
        const int ro   = half * 12 + s;
        const int prow = (ro / 3) + (ro % 3);       // compile-time per s,half
        const float4* rp4 = reinterpret_cast<const float4*>(rp[prow]);
        const float4 lo = rp4[m];
        const float4 hi = rp4[m + 1];
        float4 o;
        o.x = (r == 0) ? lo.x : (r == 1) ? lo.z : hi.x;
        o.y = (r == 0) ? lo.y : lo.w;
        o.z = (r == 2) ? hi.x : lo.z;
        o.w = (r == 0) ? lo.y : (r == 1) ? lo.w : hi.y;
        if (lastblk && prow == 9) {                 // warp-uniform, rare
            o.x *= 2.0f; o.y *= 2.0f; o.z *= 2.0f; o.w *= 2.0f;
        }
        *reinterpret_cast<float4*>(ob + (size_t)s * OW) = o;
    }
}

extern "C" void kernel_launch(void* const* d_in, const int* in_sizes, int n_in,
                              void* d_out, int out_size) {
    const float* x = (const float*)d_in[0];
    float* out = (float*)d_out;

    const int bc = in_sizes[0] / (H * W);   // B*C = 128
    dim3 grid(H / R, bc);                   // 32 x 128 = 4096 blocks
    dim3 block(NT);
    deform_sample_kernel<<<grid, block>>>(x, out);
}